// round 14
// baseline (speedup 1.0000x reference)
#include <cuda_runtime.h>
#include <cstdint>

#define ADAPTERS  40
#define CAPS      3
#define CLASS_DIM 200
#define IN_CH     600
#define BATCH     256
#define DOUT      768
#define PDIM      200

typedef unsigned long long ull;

// ---------------- scratch (device globals; no allocation allowed) ------------
__device__ float  g_priors[(size_t)CAPS * BATCH * ADAPTERS * PDIM]; // 24.6 MB
__device__ float  g_vote[(size_t)CAPS * BATCH * CLASS_DIM];
__device__ float4 g_gw[DOUT];

// Packed fp32x2 FMA (Blackwell FFMA2): d = a*b + d lane-wise on 2 floats.
#define FMA2(acc, a, b) \
    asm("fma.rn.f32x2 %0, %1, %2, %0;" : "+l"(acc) : "l"(a), "l"(b))
// Duplicate one fp32 into both lanes of an f32x2 (ALU-pipe mov.b64).
#define DUP2(dst, f) \
    asm("mov.b64 %0, {%1, %1};" : "=l"(dst) : "r"(__float_as_uint(f)))

// ---------------- Stage A: priors[n,b,k,d] = sum_c x[b,k,c]*rw[k,n,c,d] -----
// FFMA2 GEMM tuned for load balance: BM=128 -> 630 active blocks (4.26/SM,
// all co-resident, 1.17x tail vs R13's 1.41x; fills hidden by block overlap).
// 160 threads (32 ty x 5 tx), microtile 4 rows x 8 cols:
// per k-slice/thread: 3 LDS.128 + 4 DUP + 16 FFMA2  -> FFMA2-pipe bound.
#define BM  128
#define BN  40
#define BKC 24

__global__ __launch_bounds__(160) void priors_kernel(const int* __restrict__ t_ptr,
                                                     const float* __restrict__ x,
                                                     const float* __restrict__ rw) {
    const int k = blockIdx.y;
    const int n = blockIdx.z;
    if (k > *t_ptr) return;           // exactly-zero softmax weight downstream

    const int bt = blockIdx.x & 1;    // 2 b-tiles of 128
    const int dt = blockIdx.x >> 1;   // 5 d-tiles of 40 (exact)
    const int b0 = bt * BM;
    const int d0 = dt * BN;

    __shared__ float As[BKC * BM];    // [cc][row], 12.3 KB
    __shared__ float Bs[BKC * BN];    // [cc][dd],   3.75 KB

    const int tid = threadIdx.x;      // 0..159
    const int tx  = tid % 5;          // col group: 8 cols
    const int ty  = tid / 5;          // 0..31: 4 rows
    const int r0  = ty * 4;
    const int dc0 = tx * 8;

    ull acc[4][4];                    // [row][col-pair]
    #pragma unroll
    for (int r = 0; r < 4; r++)
        #pragma unroll
        for (int j = 0; j < 4; j++) acc[r][j] = 0ull;

    const float* xk = x  + (size_t)k * IN_CH;
    const float* wk = rw + (size_t)(k * CAPS + n) * IN_CH * CLASS_DIM;

    for (int c0 = 0; c0 < IN_CH; c0 += BKC) {
        // ---- fill A (128 rows x 24 c): row = i&127 -> STS conflict-free ----
        #pragma unroll
        for (int i = tid; i < BM * 6; i += 160) {
            int row = i & 127, c4 = (i >> 7) * 4;
            float4 v = *(const float4*)&xk[(size_t)(b0 + row) * (ADAPTERS * IN_CH)
                                           + c0 + c4];
            As[(c4 + 0) * BM + row] = v.x;
            As[(c4 + 1) * BM + row] = v.y;
            As[(c4 + 2) * BM + row] = v.z;
            As[(c4 + 3) * BM + row] = v.w;
        }
        // ---- fill B (24 c x 40 d) ----
        #pragma unroll
        for (int i = tid; i < BKC * 10; i += 160) {
            int cc = i / 10, d4 = (i % 10) * 4;
            *(float4*)&Bs[cc * BN + d4] =
                *(const float4*)&wk[(size_t)(c0 + cc) * CLASS_DIM + d0 + d4];
        }
        __syncthreads();

        #pragma unroll 8
        for (int cc = 0; cc < BKC; cc++) {
            float4 a = *(const float4*)&As[cc * BM + r0];
            ulonglong2 b01 = *(const ulonglong2*)&Bs[cc * BN + dc0];
            ulonglong2 b23 = *(const ulonglong2*)&Bs[cc * BN + dc0 + 4];
            ull ad[4];
            DUP2(ad[0], a.x); DUP2(ad[1], a.y); DUP2(ad[2], a.z); DUP2(ad[3], a.w);
            #pragma unroll
            for (int r = 0; r < 4; r++) {
                FMA2(acc[r][0], ad[r], b01.x);
                FMA2(acc[r][1], ad[r], b01.y);
                FMA2(acc[r][2], ad[r], b23.x);
                FMA2(acc[r][3], ad[r], b23.y);
            }
        }
        __syncthreads();
    }

    // ---- epilogue: pairs are d-ordered -> 2 float4 stores per row ----
    #pragma unroll
    for (int r = 0; r < 4; r++) {
        float* dst = &g_priors[(((size_t)n * BATCH + b0 + r0 + r) * ADAPTERS + k)
                               * PDIM + d0 + dc0];
        float4 o0, o1;
        o0.x = __uint_as_float((unsigned)(acc[r][0] & 0xffffffffu));
        o0.y = __uint_as_float((unsigned)(acc[r][0] >> 32));
        o0.z = __uint_as_float((unsigned)(acc[r][1] & 0xffffffffu));
        o0.w = __uint_as_float((unsigned)(acc[r][1] >> 32));
        o1.x = __uint_as_float((unsigned)(acc[r][2] & 0xffffffffu));
        o1.y = __uint_as_float((unsigned)(acc[r][2] >> 32));
        o1.z = __uint_as_float((unsigned)(acc[r][3] & 0xffffffffu));
        o1.w = __uint_as_float((unsigned)(acc[r][3] >> 32));
        *(float4*)(dst)     = o0;
        *(float4*)(dst + 4) = o1;
    }
}

// ---------------- Stage B: dynamic routing (3 iterations) --------------------
__global__ void routing_kernel(const int* __restrict__ t_ptr,
                               const float* __restrict__ tsv) {
    const int b   = blockIdx.x;
    const int n   = blockIdx.y;
    const int t   = *t_ptr;
    const int nk  = t + 1;
    const int tid = threadIdx.x;

    __shared__ float sp[ADAPTERS][CLASS_DIM]; // 32 KB
    __shared__ float sout[CLASS_DIM];
    __shared__ float sL[ADAPTERS];
    __shared__ float sprob[ADAPTERS];
    __shared__ float stw[ADAPTERS];
    __shared__ float red[256];

    const float* pbase = g_priors + (((size_t)n * BATCH + b) * ADAPTERS) * PDIM;
    for (int i = tid; i < nk * CLASS_DIM; i += 256)
        sp[i / CLASS_DIM][i % CLASS_DIM] = pbase[i];   // PDIM == CLASS_DIM

    if (tid < ADAPTERS) {
        sL[tid]  = 0.f;
        stw[tid] = tsv[t * ADAPTERS + tid];
    }
    __syncthreads();

    for (int it = 0; it < 3; it++) {
        if (tid == 0) {
            float mx = -1e30f;
            for (int kk = 0; kk < nk; kk++) {
                float tw = stw[kk];
                float L  = sL[kk] * tw + (tw == 0.f ? -10000.f : 0.f);
                sL[kk] = L;
                mx = fmaxf(mx, L);
            }
            float s = 0.f;
            for (int kk = 0; kk < nk; kk++) {
                float e = expf(sL[kk] - mx);
                sprob[kk] = e;
                s += e;
            }
            float inv = 1.f / s;
            for (int kk = 0; kk < nk; kk++) sprob[kk] *= inv;
        }
        __syncthreads();

        float v = 0.f;
        if (tid < CLASS_DIM)
            for (int kk = 0; kk < nk; kk++) v += sprob[kk] * sp[kk][tid];

        red[tid] = (tid < CLASS_DIM) ? v * v : 0.f;
        __syncthreads();
        for (int s = 128; s > 0; s >>= 1) {
            if (tid < s) red[tid] += red[tid + s];
            __syncthreads();
        }
        float sq = red[0];

        if (it == 2) {
            if (tid < CLASS_DIM)
                g_vote[((size_t)n * BATCH + b) * CLASS_DIM + tid] = v;
        } else {
            float scale = sq / (1.f + sq) * rsqrtf(sq);
            if (tid < CLASS_DIM) sout[tid] = v * scale;
            __syncthreads();
            int wd = tid >> 5, lane = tid & 31;
            for (int kk = wd; kk < nk; kk += 8) {
                float p = 0.f;
                for (int d = lane; d < CLASS_DIM; d += 32) p += sp[kk][d] * sout[d];
                #pragma unroll
                for (int off = 16; off; off >>= 1)
                    p += __shfl_down_sync(0xffffffffu, p, off);
                if (lane == 0) sL[kk] += p;
            }
            __syncthreads();
        }
    }
}

// ---------------- Stage pre-C: fold gate into weights ------------------------
__global__ void gw_kernel(const int* __restrict__ t_ptr,
                          const float* __restrict__ s,
                          const float* __restrict__ lw,
                          const float* __restrict__ lb,
                          const float* __restrict__ elarger) {
    int j = blockIdx.x * 256 + threadIdx.x;
    if (j >= DOUT) return;
    int t = *t_ptr;
    float g = 1.f / (1.f + expf(-s[0] * elarger[t * DOUT + j]));
    float4 w;
    w.x = g * lw[j * 3 + 0];
    w.y = g * lw[j * 3 + 1];
    w.z = g * lw[j * 3 + 2];
    w.w = g * lb[j];
    g_gw[j] = w;
}

// ---------------- Stage C: out[row, j] = sum_c h_c * gw[j].c + gw[j].w -------
__global__ void out_kernel(float* __restrict__ out) {
    const int tid = threadIdx.x;       // 0..191
    float4 w[4];
    #pragma unroll
    for (int q = 0; q < 4; q++) w[q] = g_gw[tid * 4 + q];

    size_t row = (size_t)blockIdx.x * 8;
    #pragma unroll
    for (int r = 0; r < 8; r++, row++) {
        float v0 = g_vote[row * 3 + 0];
        float v1 = g_vote[row * 3 + 1];
        float v2 = g_vote[row * 3 + 2];
        float4 res;
        res.x = v0 * w[0].x + v1 * w[0].y + v2 * w[0].z + w[0].w;
        res.y = v0 * w[1].x + v1 * w[1].y + v2 * w[1].z + w[1].w;
        res.z = v0 * w[2].x + v1 * w[2].y + v2 * w[2].z + w[2].w;
        res.w = v0 * w[3].x + v1 * w[3].y + v2 * w[3].z + w[3].w;
        __stcs(((float4*)(out + row * DOUT)) + tid, res);
    }
}

// ---------------- launch -----------------------------------------------------
extern "C" void kernel_launch(void* const* d_in, const int* in_sizes, int n_in,
                              void* d_out, int out_size) {
    const int*   t_ptr   = (const int*)  d_in[0];
    const float* x       = (const float*)d_in[1];
    const float* s       = (const float*)d_in[2];
    const float* rw      = (const float*)d_in[3];
    const float* lw      = (const float*)d_in[4];
    const float* lb      = (const float*)d_in[5];
    const float* elarger = (const float*)d_in[6];
    const float* tsv     = (const float*)d_in[7];
    float* out = (float*)d_out;

    priors_kernel<<<dim3(10, ADAPTERS, CAPS), 160>>>(t_ptr, x, rw);
    routing_kernel<<<dim3(BATCH, CAPS), 256>>>(t_ptr, tsv);
    gw_kernel<<<3, 256>>>(t_ptr, s, lw, lb, elarger);
    out_kernel<<<(BATCH * CLASS_DIM) / 8, 192>>>(out);
}

// round 16
// speedup vs baseline: 1.4302x; 1.4302x over previous
#include <cuda_runtime.h>
#include <cstdint>

#define ADAPTERS  40
#define CAPS      3
#define CLASS_DIM 200
#define IN_CH     600
#define BATCH     256
#define DOUT      768
#define PDIM      200

typedef unsigned long long ull;

// ---------------- scratch (device globals; no allocation allowed) ------------
__device__ float  g_priors[(size_t)CAPS * BATCH * ADAPTERS * PDIM]; // 24.6 MB
__device__ float  g_xt[(size_t)ADAPTERS * IN_CH * BATCH];           // 24.6 MB x^T
__device__ float  g_vote[(size_t)CAPS * BATCH * CLASS_DIM];
__device__ float4 g_gw[DOUT];

// Packed fp32x2 FMA (Blackwell FFMA2): d = a*b + d lane-wise on 2 floats.
#define FMA2(acc, a, b) \
    asm("fma.rn.f32x2 %0, %1, %2, %0;" : "+l"(acc) : "l"(a), "l"(b))
// Duplicate one fp32 into both lanes of an f32x2 (ALU-pipe mov.b64).
#define DUP2(dst, f) \
    asm("mov.b64 %0, {%1, %1};" : "=l"(dst) : "r"(__float_as_uint(f)))

__device__ __forceinline__ uint32_t smem_u32(const void* p) {
    uint32_t a;
    asm("{ .reg .u64 t; cvta.to.shared.u64 t, %1; cvt.u32.u64 %0, t; }"
        : "=r"(a) : "l"(p));
    return a;
}
__device__ __forceinline__ void cpa16(uint32_t s, const float* g) {
    asm volatile("cp.async.ca.shared.global [%0], [%1], 16;" :: "r"(s), "l"(g));
}
#define CPA_COMMIT()  asm volatile("cp.async.commit_group;" ::: "memory")
#define CPA_WAIT(n)   asm volatile("cp.async.wait_group %0;" :: "n"(n) : "memory")

// ---------------- Stage A0: transpose x[b,k,c] -> xt[k][c][b] ---------------
// Makes priors' A tiles contiguous (1KB rows) so they can be cp.async'd.
__global__ __launch_bounds__(256) void xt_kernel(const int* __restrict__ t_ptr,
                                                 const float* __restrict__ x) {
    const int k = blockIdx.z;
    if (k > *t_ptr) return;
    const int cb = blockIdx.x * 32;
    const int bb = blockIdx.y * 32;
    __shared__ float tile[32][33];

    const int tx = threadIdx.x, ty = threadIdx.y;   // 32 x 8
    #pragma unroll
    for (int j = 0; j < 4; j++) {
        int c = cb + tx, b = bb + ty + j * 8;
        if (c < IN_CH)
            tile[ty + j * 8][tx] = x[(size_t)b * (ADAPTERS * IN_CH) + k * IN_CH + c];
    }
    __syncthreads();
    #pragma unroll
    for (int j = 0; j < 4; j++) {
        int c = cb + ty + j * 8, b = bb + tx;
        if (c < IN_CH)
            g_xt[((size_t)k * IN_CH + c) * BATCH + b] = tile[tx][ty + j * 8];
    }
}

// ---------------- Stage A: priors[n,b,k,d] = sum_c x[b,k,c]*rw[k,n,c,d] -----
// FFMA2 GEMM, cp.async double-buffered. BM=256 (whole batch), BN=40, BKC=20
// (600 = 30*20). 160 threads (32 ty x 5 tx), microtile 8 rows x 8 cols:
// per k-slice/thread 4 LDS.128 + 8 DUP + 32 FFMA2. Fills fully async.
#define BM   256
#define BN   40
#define BKC  20
#define NCH  30

__global__ __launch_bounds__(160) void priors_kernel(const int* __restrict__ t_ptr,
                                                     const float* __restrict__ rw) {
    const int k = blockIdx.y;
    const int n = blockIdx.z;
    if (k > *t_ptr) return;           // exactly-zero softmax weight downstream

    const int d0 = blockIdx.x * BN;   // 5 d-tiles of 40 (exact)

    __shared__ float As[2][BKC * BM]; // [cc][row], 20 KB per stage
    __shared__ float Bs[2][BKC * BN]; // [cc][dd],  3.125 KB per stage

    const int tid = threadIdx.x;      // 0..159
    const int tx  = tid % 5;
    const int ty  = tid / 5;
    const int r0  = ty * 8;
    const int dc0 = tx * 8;

    const float* xk = g_xt + (size_t)k * IN_CH * BATCH;
    const float* wk = rw + (size_t)(k * CAPS + n) * IN_CH * CLASS_DIM;

    const uint32_t asb[2] = { smem_u32(As[0]), smem_u32(As[1]) };
    const uint32_t bsb[2] = { smem_u32(Bs[0]), smem_u32(Bs[1]) };

    // Issue one chunk's async copies into stage s.
    auto issue = [&](int ch, int s) {
        const int c0 = ch * BKC;
        // A: 20 rows x 256 floats = 1280 16B units; 8 per thread
        #pragma unroll
        for (int i = tid; i < BKC * 64; i += 160) {
            int cc = i >> 6, off = (i & 63) * 4;
            cpa16(asb[s] + (cc * BM + off) * 4, &xk[(size_t)(c0 + cc) * BATCH + off]);
        }
        // B: 20 rows x 40 floats = 200 16B units
        #pragma unroll
        for (int i = tid; i < BKC * 10; i += 160) {
            int cc = i / 10, d4 = (i % 10) * 4;
            cpa16(bsb[s] + (cc * BN + d4) * 4, &wk[(size_t)(c0 + cc) * CLASS_DIM + d0 + d4]);
        }
        CPA_COMMIT();
    };

    ull acc[8][4];
    #pragma unroll
    for (int r = 0; r < 8; r++)
        #pragma unroll
        for (int j = 0; j < 4; j++) acc[r][j] = 0ull;

    issue(0, 0);
    for (int ch = 0; ch < NCH; ch++) {
        const int s = ch & 1;
        if (ch + 1 < NCH) { issue(ch + 1, s ^ 1); CPA_WAIT(1); }
        else              { CPA_WAIT(0); }
        __syncthreads();

        const float* A = As[s];
        const float* B = Bs[s];
        #pragma unroll 5
        for (int cc = 0; cc < BKC; cc++) {
            float4 a0 = *(const float4*)&A[cc * BM + r0];
            float4 a1 = *(const float4*)&A[cc * BM + r0 + 4];
            ulonglong2 b01 = *(const ulonglong2*)&B[cc * BN + dc0];
            ulonglong2 b23 = *(const ulonglong2*)&B[cc * BN + dc0 + 4];
            ull ad[8];
            DUP2(ad[0], a0.x); DUP2(ad[1], a0.y); DUP2(ad[2], a0.z); DUP2(ad[3], a0.w);
            DUP2(ad[4], a1.x); DUP2(ad[5], a1.y); DUP2(ad[6], a1.z); DUP2(ad[7], a1.w);
            #pragma unroll
            for (int r = 0; r < 8; r++) {
                FMA2(acc[r][0], ad[r], b01.x);
                FMA2(acc[r][1], ad[r], b01.y);
                FMA2(acc[r][2], ad[r], b23.x);
                FMA2(acc[r][3], ad[r], b23.y);
            }
        }
        __syncthreads();   // all reads of stage s done before it is refilled
    }

    // ---- epilogue: pairs are d-ordered -> 2 float4 stores per row ----
    #pragma unroll
    for (int r = 0; r < 8; r++) {
        float* dst = &g_priors[(((size_t)n * BATCH + r0 + r) * ADAPTERS + k) * PDIM
                               + d0 + dc0];
        float4 o0, o1;
        o0.x = __uint_as_float((unsigned)(acc[r][0] & 0xffffffffu));
        o0.y = __uint_as_float((unsigned)(acc[r][0] >> 32));
        o0.z = __uint_as_float((unsigned)(acc[r][1] & 0xffffffffu));
        o0.w = __uint_as_float((unsigned)(acc[r][1] >> 32));
        o1.x = __uint_as_float((unsigned)(acc[r][2] & 0xffffffffu));
        o1.y = __uint_as_float((unsigned)(acc[r][2] >> 32));
        o1.z = __uint_as_float((unsigned)(acc[r][3] & 0xffffffffu));
        o1.w = __uint_as_float((unsigned)(acc[r][3] >> 32));
        *(float4*)(dst)     = o0;
        *(float4*)(dst + 4) = o1;
    }
}

// ---------------- Stage B: dynamic routing (3 iterations) --------------------
__global__ void routing_kernel(const int* __restrict__ t_ptr,
                               const float* __restrict__ tsv) {
    const int b   = blockIdx.x;
    const int n   = blockIdx.y;
    const int t   = *t_ptr;
    const int nk  = t + 1;
    const int tid = threadIdx.x;

    __shared__ float sp[ADAPTERS][CLASS_DIM]; // 32 KB
    __shared__ float sout[CLASS_DIM];
    __shared__ float sL[ADAPTERS];
    __shared__ float sprob[ADAPTERS];
    __shared__ float stw[ADAPTERS];
    __shared__ float red[256];

    const float* pbase = g_priors + (((size_t)n * BATCH + b) * ADAPTERS) * PDIM;
    for (int i = tid; i < nk * CLASS_DIM; i += 256)
        sp[i / CLASS_DIM][i % CLASS_DIM] = pbase[i];

    if (tid < ADAPTERS) {
        sL[tid]  = 0.f;
        stw[tid] = tsv[t * ADAPTERS + tid];
    }
    __syncthreads();

    for (int it = 0; it < 3; it++) {
        if (tid == 0) {
            float mx = -1e30f;
            for (int kk = 0; kk < nk; kk++) {
                float tw = stw[kk];
                float L  = sL[kk] * tw + (tw == 0.f ? -10000.f : 0.f);
                sL[kk] = L;
                mx = fmaxf(mx, L);
            }
            float s = 0.f;
            for (int kk = 0; kk < nk; kk++) {
                float e = expf(sL[kk] - mx);
                sprob[kk] = e;
                s += e;
            }
            float inv = 1.f / s;
            for (int kk = 0; kk < nk; kk++) sprob[kk] *= inv;
        }
        __syncthreads();

        float v = 0.f;
        if (tid < CLASS_DIM)
            for (int kk = 0; kk < nk; kk++) v += sprob[kk] * sp[kk][tid];

        red[tid] = (tid < CLASS_DIM) ? v * v : 0.f;
        __syncthreads();
        for (int s = 128; s > 0; s >>= 1) {
            if (tid < s) red[tid] += red[tid + s];
            __syncthreads();
        }
        float sq = red[0];

        if (it == 2) {
            if (tid < CLASS_DIM)
                g_vote[((size_t)n * BATCH + b) * CLASS_DIM + tid] = v;
        } else {
            float scale = sq / (1.f + sq) * rsqrtf(sq);
            if (tid < CLASS_DIM) sout[tid] = v * scale;
            __syncthreads();
            int wd = tid >> 5, lane = tid & 31;
            for (int kk = wd; kk < nk; kk += 8) {
                float p = 0.f;
                for (int d = lane; d < CLASS_DIM; d += 32) p += sp[kk][d] * sout[d];
                #pragma unroll
                for (int off = 16; off; off >>= 1)
                    p += __shfl_down_sync(0xffffffffu, p, off);
                if (lane == 0) sL[kk] += p;
            }
            __syncthreads();
        }
    }
}

// ---------------- Stage pre-C: fold gate into weights ------------------------
__global__ void gw_kernel(const int* __restrict__ t_ptr,
                          const float* __restrict__ s,
                          const float* __restrict__ lw,
                          const float* __restrict__ lb,
                          const float* __restrict__ elarger) {
    int j = blockIdx.x * 256 + threadIdx.x;
    if (j >= DOUT) return;
    int t = *t_ptr;
    float g = 1.f / (1.f + expf(-s[0] * elarger[t * DOUT + j]));
    float4 w;
    w.x = g * lw[j * 3 + 0];
    w.y = g * lw[j * 3 + 1];
    w.z = g * lw[j * 3 + 2];
    w.w = g * lb[j];
    g_gw[j] = w;
}

// ---------------- Stage C: out[row, j] = sum_c h_c * gw[j].c + gw[j].w -------
__global__ void out_kernel(float* __restrict__ out) {
    const int tid = threadIdx.x;       // 0..191
    float4 w[4];
    #pragma unroll
    for (int q = 0; q < 4; q++) w[q] = g_gw[tid * 4 + q];

    size_t row = (size_t)blockIdx.x * 8;
    #pragma unroll
    for (int r = 0; r < 8; r++, row++) {
        float v0 = g_vote[row * 3 + 0];
        float v1 = g_vote[row * 3 + 1];
        float v2 = g_vote[row * 3 + 2];
        float4 res;
        res.x = v0 * w[0].x + v1 * w[0].y + v2 * w[0].z + w[0].w;
        res.y = v0 * w[1].x + v1 * w[1].y + v2 * w[1].z + w[1].w;
        res.z = v0 * w[2].x + v1 * w[2].y + v2 * w[2].z + w[2].w;
        res.w = v0 * w[3].x + v1 * w[3].y + v2 * w[3].z + w[3].w;
        __stcs(((float4*)(out + row * DOUT)) + tid, res);
    }
}

// ---------------- launch -----------------------------------------------------
extern "C" void kernel_launch(void* const* d_in, const int* in_sizes, int n_in,
                              void* d_out, int out_size) {
    const int*   t_ptr   = (const int*)  d_in[0];
    const float* x       = (const float*)d_in[1];
    const float* s       = (const float*)d_in[2];
    const float* rw      = (const float*)d_in[3];
    const float* lw      = (const float*)d_in[4];
    const float* lb      = (const float*)d_in[5];
    const float* elarger = (const float*)d_in[6];
    const float* tsv     = (const float*)d_in[7];
    float* out = (float*)d_out;

    xt_kernel<<<dim3(19, 8, ADAPTERS), dim3(32, 8)>>>(t_ptr, x);
    priors_kernel<<<dim3(5, ADAPTERS, CAPS), 160>>>(t_ptr, rw);
    routing_kernel<<<dim3(BATCH, CAPS), 256>>>(t_ptr, tsv);
    gw_kernel<<<3, 256>>>(t_ptr, s, lw, lb, elarger);
    out_kernel<<<(BATCH * CLASS_DIM) / 8, 192>>>(out);
}